// round 2
// baseline (speedup 1.0000x reference)
#include <cuda_runtime.h>
#include <cuda_bf16.h>

#define BATCH   8
#define HID     256
#define DINNER  512
#define DSTATE  16
#define DTRANK  16
#define LSEQ    1024
#define NPIX    (BATCH*LSEQ)

// ---------------- scratch (device globals) ----------------
__device__ float g_silut[BATCH*1024];
__device__ float g_mod  [BATCH*6*HID];
__device__ float g_xht  [NPIX*HID];
__device__ float g_h1   [NPIX*HID];
__device__ float g_xm   [BATCH*DINNER*LSEQ];          // NCHW
__device__ float g_z    [NPIX*DINNER];                // (B,L,512)
__device__ float g_xc   [BATCH*DINNER*LSEQ];          // NCHW
__device__ float g_xs   [BATCH*4*LSEQ*DINNER];        // (b,k,l,d)
__device__ float g_xdbl [BATCH*4*LSEQ*48];            // (b,k,l,48)
__device__ float g_ys   [BATCH*4*LSEQ*DINNER];        // (b,k,l,d)
__device__ float g_yln  [NPIX*DINNER];
__device__ float g_xh1  [NPIX*HID];
__device__ float g_h2   [NPIX*HID];
__device__ float g_qkv1 [BATCH*768*LSEQ];
__device__ float g_qkv2 [BATCH*768*LSEQ];
__device__ float g_attno[NPIX*HID];
__device__ float g_projo[NPIX*HID];
__device__ float g_qkvwT[256*768];
__device__ float g_projwT[256*256];
__device__ float g_xprojT[4*512*48];

// ---------------- fast exp ----------------
__device__ __forceinline__ float exp2_fast(float y){
    y = fminf(fmaxf(y, -126.f), 126.f);
    float r = rintf(y);
    float f = y - r;
    float p =              1.5403530e-4f;
    p = fmaf(p, f, 1.3333558e-3f);
    p = fmaf(p, f, 9.6181291e-3f);
    p = fmaf(p, f, 5.5504109e-2f);
    p = fmaf(p, f, 2.4022651e-1f);
    p = fmaf(p, f, 6.9314718e-1f);
    p = fmaf(p, f, 1.0f);
    return p * __int_as_float(((int)r + 127) << 23);
}
__device__ __forceinline__ float exp_fast(float x){ return exp2_fast(x * 1.4426950408889634f); }

// ---------------- small kernels ----------------
__global__ void silu_t_k(const float* __restrict__ t){
    int i = blockIdx.x*blockDim.x + threadIdx.x;
    if (i < BATCH*1024){ float v = t[i]; g_silut[i] = v/(1.f+expf(-v)); }
}

__global__ void transpose_w_k(const float* __restrict__ in, float* __restrict__ out, int R, int C){
    int z = blockIdx.y;
    const float* ip = in + (long)z*R*C;
    float* op = out + (long)z*R*C;
    int i = blockIdx.x*blockDim.x + threadIdx.x;
    if (i < R*C){ int r = i/C, c = i%C; op[c*R + r] = ip[i]; }
}

__global__ void transpose_x_k(const float* __restrict__ x){
    __shared__ float tile[32][33];
    int b = blockIdx.z, l0 = blockIdx.x*32, c0 = blockIdx.y*32;
    int tx = threadIdx.x, ty = threadIdx.y;
#pragma unroll
    for (int j=0;j<4;j++)
        tile[ty+j*8][tx] = x[((long)(b*HID + c0+ty+j*8))<<10 | (l0+tx)];
    __syncthreads();
#pragma unroll
    for (int j=0;j<4;j++)
        g_xht[((long)(b*LSEQ + l0+ty+j*8))*HID + c0+tx] = tile[tx][ty+j*8];
}

// LN + modulate; one warp per pixel
__global__ void ln_mod_k(const float* __restrict__ xin, const float* __restrict__ g,
                         const float* __restrict__ bt, int sh_off, int sc_off,
                         float eps, int affine, float* __restrict__ out){
    int warp = threadIdx.x>>5, lane = threadIdx.x&31;
    int pix = blockIdx.x*8 + warp, b = pix>>10;
    const float* row = xin + (long)pix*HID;
    float v[8]; float s=0.f, sq=0.f;
#pragma unroll
    for (int i=0;i<8;i++){ v[i]=row[lane+i*32]; s+=v[i]; sq+=v[i]*v[i]; }
#pragma unroll
    for (int o=16;o;o>>=1){ s+=__shfl_xor_sync(~0u,s,o); sq+=__shfl_xor_sync(~0u,sq,o); }
    float mu = s*(1.f/HID), var = sq*(1.f/HID)-mu*mu, rstd = rsqrtf(var+eps);
#pragma unroll
    for (int i=0;i<8;i++){
        int ch = lane+i*32;
        float y = (v[i]-mu)*rstd;
        if (affine) y = y*g[ch]+bt[ch];
        out[(long)pix*HID+ch] = y*(1.f+g_mod[b*1536+sc_off+ch]) + g_mod[b*1536+sh_off+ch];
    }
}

// ---------------- GEMM 64x64x16, 4x4/thread ----------------
// modes: 0 plain, 1 xm/z split, 2 residual+gate, 3 NCHW scatter(768), 5 bias
__global__ void gemm_kernel(const float* __restrict__ A, const float* __restrict__ B,
                            float* __restrict__ C, float* __restrict__ C2,
                            const float* __restrict__ aux0, const float* __restrict__ aux1,
                            int M, int N, int K, int lda, int ldb,
                            long Astride, long Bstride, long Cstride, int bmod, int mode){
    __shared__ float sA[16][64];
    __shared__ float sB[16][64];
    int z = blockIdx.z;
    A += (long)z*Astride;
    B += (long)(bmod ? (z % bmod) : z)*Bstride;
    int bn = blockIdx.x*64, bm = blockIdx.y*64;
    int tid = threadIdx.x, tx = tid&15, ty = tid>>4;
    float acc[4][4];
#pragma unroll
    for (int i=0;i<4;i++)
#pragma unroll
        for (int j=0;j<4;j++) acc[i][j]=0.f;

    for (int k0=0;k0<K;k0+=16){
        int am = bm + (tid>>2), ak0 = (tid&3)<<2;
        float4 av = make_float4(0.f,0.f,0.f,0.f);
        if (am < M) av = *(const float4*)&A[(long)am*lda + k0 + ak0];
        sA[ak0+0][tid>>2]=av.x; sA[ak0+1][tid>>2]=av.y;
        sA[ak0+2][tid>>2]=av.z; sA[ak0+3][tid>>2]=av.w;
        int bkk = tid>>4, bn0 = (tid&15)<<2;
        const float* Brow = &B[(long)(k0+bkk)*ldb + bn + bn0];
#pragma unroll
        for (int u=0;u<4;u++)
            sB[bkk][bn0+u] = (bn+bn0+u < N) ? Brow[u] : 0.f;
        __syncthreads();
#pragma unroll
        for (int kk=0;kk<16;kk++){
            float4 a = *(const float4*)&sA[kk][ty*4];
            float4 bv= *(const float4*)&sB[kk][tx*4];
            acc[0][0]=fmaf(a.x,bv.x,acc[0][0]); acc[0][1]=fmaf(a.x,bv.y,acc[0][1]);
            acc[0][2]=fmaf(a.x,bv.z,acc[0][2]); acc[0][3]=fmaf(a.x,bv.w,acc[0][3]);
            acc[1][0]=fmaf(a.y,bv.x,acc[1][0]); acc[1][1]=fmaf(a.y,bv.y,acc[1][1]);
            acc[1][2]=fmaf(a.y,bv.z,acc[1][2]); acc[1][3]=fmaf(a.y,bv.w,acc[1][3]);
            acc[2][0]=fmaf(a.z,bv.x,acc[2][0]); acc[2][1]=fmaf(a.z,bv.y,acc[2][1]);
            acc[2][2]=fmaf(a.z,bv.z,acc[2][2]); acc[2][3]=fmaf(a.z,bv.w,acc[2][3]);
            acc[3][0]=fmaf(a.w,bv.x,acc[3][0]); acc[3][1]=fmaf(a.w,bv.y,acc[3][1]);
            acc[3][2]=fmaf(a.w,bv.z,acc[3][2]); acc[3][3]=fmaf(a.w,bv.w,acc[3][3]);
        }
        __syncthreads();
    }
#pragma unroll
    for (int i=0;i<4;i++){
        int m = bm + ty*4 + i;
        if (m >= M) continue;
        int b = m>>10, l = m&1023;
#pragma unroll
        for (int j=0;j<4;j++){
            int n = bn + tx*4 + j;
            if (n >= N) continue;
            float v = acc[i][j];
            switch (mode){
            case 0: C[z*Cstride + (long)m*N + n] = v; break;
            case 1:
                if (n < 512) C[((long)(b*512+n)<<10) + l] = v;
                else         C2[(long)m*512 + (n-512)] = v;
                break;
            case 2: C[(long)m*256+n] = aux0[(long)m*256+n] + aux1[b*1536+n]*v; break;
            case 3: C[((long)(b*768+n)<<10) + l] = v; break;
            case 5: C[(long)m*N+n] = v + aux0[n]; break;
            }
        }
    }
}

// ---------------- depthwise 3x3 SAME ----------------
__global__ void dwconv_k(const float* __restrict__ in, const float* __restrict__ w,
                         const float* __restrict__ bias, float* __restrict__ out,
                         int C, int act){
    int bc = blockIdx.x, ch = bc % C;
    const float* p = in + (long)bc*LSEQ;
    const float* wc = w + ch*9;
    float w0=wc[0],w1=wc[1],w2=wc[2],w3=wc[3],w4=wc[4],w5=wc[5],w6=wc[6],w7=wc[7],w8=wc[8];
    float bv = bias ? bias[ch] : 0.f;
    for (int idx = threadIdx.x; idx < LSEQ; idx += blockDim.x){
        int y = idx>>5, x = idx&31;
        float s = bv;
        bool yu=y>0, yd=y<31, xl=x>0, xr=x<31;
        if (yu){ if (xl) s=fmaf(w0,p[idx-33],s); s=fmaf(w1,p[idx-32],s); if (xr) s=fmaf(w2,p[idx-31],s); }
        if (xl) s=fmaf(w3,p[idx-1],s);
        s=fmaf(w4,p[idx],s);
        if (xr) s=fmaf(w5,p[idx+1],s);
        if (yd){ if (xl) s=fmaf(w6,p[idx+31],s); s=fmaf(w7,p[idx+32],s); if (xr) s=fmaf(w8,p[idx+33],s); }
        if (act) s = s/(1.f+expf(-s));
        out[(long)bc*LSEQ + idx] = s;
    }
}

// ---------------- build xs (b,k,l,d) ----------------
__device__ __forceinline__ int lmap_dir(int k, int i){
    int ti = ((i&31)<<5) | (i>>5);
    if (k==0) return i;
    if (k==1) return ti;
    if (k==2) return 1023-i;
    return 1023-ti;
}
__global__ void build_xs_k(void){
    __shared__ float tile[32][33];
    int bk = blockIdx.z, b = bk>>2, k = bk&3;
    int i0 = blockIdx.x*32, d0 = blockIdx.y*32;
    int tx = threadIdx.x, ty = threadIdx.y;
#pragma unroll
    for (int j=0;j<4;j++)
        tile[ty+j*8][tx] = g_xc[((long)(b*DINNER + d0+ty+j*8))<<10 | (i0+tx)];
    __syncthreads();
#pragma unroll
    for (int j=0;j<4;j++){
        int l = lmap_dir(k, i0+ty+j*8);
        g_xs[(((long)bk<<10) + l)*DINNER + d0+tx] = tile[tx][ty+j*8];
    }
}

// ---------------- selective scan ----------------
__global__ void __launch_bounds__(128, 1)
scan_kernel(const float* __restrict__ dt_w, const float* __restrict__ dt_b,
            const float* __restrict__ A_logs, const float* __restrict__ Ds){
    int blk = blockIdx.x;
    int bk = blk>>2, sub = blk&3, k = bk&3;
    int d = sub*128 + threadIdx.x;
    int gd = k*DINNER + d;
    float w[DTRANK];
#pragma unroll
    for (int r=0;r<DTRANK;r++) w[r] = dt_w[gd*DTRANK+r];
    float bias = dt_b[gd];
    float A2[DSTATE];
#pragma unroll
    for (int n=0;n<DSTATE;n++) A2[n] = -expf(A_logs[gd*DSTATE+n]) * 1.4426950408889634f;
    float Dv = Ds[gd];
    float h[DSTATE];
#pragma unroll
    for (int n=0;n<DSTATE;n++) h[n]=0.f;

    const float* xrow = g_xs   + ((long)bk<<10)*DINNER;
    const float* drow = g_xdbl + ((long)bk<<10)*48;
    float*       yrow = g_ys   + ((long)bk<<10)*DINNER;

    __shared__ float sd[2][48];
    if (threadIdx.x < 48) sd[0][threadIdx.x] = drow[threadIdx.x];
    __syncthreads();
    float xnext = xrow[d];

    for (int l=0;l<LSEQ;l++){
        int cur = l&1;
        if (l+1 < LSEQ && threadIdx.x < 48)
            sd[cur^1][threadIdx.x] = drow[(l+1)*48 + threadIdx.x];
        float x = xnext;
        if (l+1 < LSEQ) xnext = xrow[(l+1)*DINNER + d];
        float v = bias;
#pragma unroll
        for (int r=0;r<DTRANK;r++) v = fmaf(sd[cur][r], w[r], v);
        float dt = fmaxf(v,0.f) + log1pf(exp_fast(-fabsf(v)));
        float dtx = dt*x;
        float y = Dv*x;
#pragma unroll
        for (int n=0;n<DSTATE;n++){
            float dA = exp2_fast(dt*A2[n]);
            h[n] = fmaf(dA, h[n], dtx*sd[cur][16+n]);
            y = fmaf(h[n], sd[cur][32+n], y);
        }
        yrow[l*DINNER + d] = y;
        __syncthreads();
    }
}

// ---------------- combine dirs + LN + silu(z) gate ----------------
__global__ void combine_ln_k(const float* __restrict__ og, const float* __restrict__ ob){
    int bl = blockIdx.x, b = bl>>10, l = bl&1023;
    int lt = ((l&31)<<5) | (l>>5);
    const float* r0 = g_ys + (((long)(b*4+0)<<10) + l)        *DINNER;
    const float* r1 = g_ys + (((long)(b*4+1)<<10) + lt)       *DINNER;
    const float* r2 = g_ys + (((long)(b*4+2)<<10) + (1023-l)) *DINNER;
    const float* r3 = g_ys + (((long)(b*4+3)<<10) + (1023-lt))*DINNER;
    float v[4]; float s=0.f, sq=0.f;
#pragma unroll
    for (int i=0;i<4;i++){
        int d = threadIdx.x + i*128;
        v[i] = r0[d]+r1[d]+r2[d]+r3[d];
        s += v[i]; sq += v[i]*v[i];
    }
    __shared__ float red[2][4];
    int warp = threadIdx.x>>5, lane = threadIdx.x&31;
#pragma unroll
    for (int o=16;o;o>>=1){ s+=__shfl_xor_sync(~0u,s,o); sq+=__shfl_xor_sync(~0u,sq,o); }
    if (!lane){ red[0][warp]=s; red[1][warp]=sq; }
    __syncthreads();
    s = red[0][0]+red[0][1]+red[0][2]+red[0][3];
    sq= red[1][0]+red[1][1]+red[1][2]+red[1][3];
    float mu = s*(1.f/DINNER), var = sq*(1.f/DINNER)-mu*mu, rstd = rsqrtf(var+1e-5f);
#pragma unroll
    for (int i=0;i<4;i++){
        int d = threadIdx.x + i*128;
        float y = (v[i]-mu)*rstd*og[d] + ob[d];
        float zz = g_z[(long)bl*DINNER + d];
        g_yln[(long)bl*DINNER + d] = y * (zz/(1.f+expf(-zz)));
    }
}

// ---------------- transposed attention ----------------
__global__ void attn_kernel(const float* __restrict__ temp){
    int b = blockIdx.x>>3, hd = blockIdx.x&7;
    const float* Q  = g_qkv2 + ((long)(b*768) + hd*32)*LSEQ;
    const float* Kp = Q + 256*LSEQ;
    const float* V  = Q + 512*LSEQ;
    __shared__ float sn[64];
    __shared__ float sS[32][33];
    __shared__ float sT0[32][128];
    __shared__ float sT1t[128][33];
    int tid = threadIdx.x, warp = tid>>5, lane = tid&31;

    // row norms: Q rows 0..31, K rows 32..63
#pragma unroll
    for (int rr=0;rr<8;rr++){
        int row = warp*8 + rr;
        const float* base = (row<32) ? (Q + row*LSEQ) : (Kp + (row-32)*LSEQ);
        float s = 0.f;
        for (int i=lane;i<LSEQ;i+=32){ float x = base[i]; s = fmaf(x,x,s); }
#pragma unroll
        for (int o=16;o;o>>=1) s += __shfl_xor_sync(~0u,s,o);
        if (!lane) sn[row] = fmaxf(sqrtf(s), 1e-12f);
    }
    __syncthreads();

    // S = Q K^T
    float acc[4] = {0.f,0.f,0.f,0.f};
    for (int l0=0;l0<LSEQ;l0+=128){
#pragma unroll
        for (int t=0;t<4;t++){
            int idx = tid + t*256;
            int row = idx>>5, c4 = (idx&31)<<2;
            float4 qv = *(const float4*)&Q [row*LSEQ + l0 + c4];
            float4 kv = *(const float4*)&Kp[row*LSEQ + l0 + c4];
            *(float4*)&sT0[row][c4] = qv;
            sT1t[c4+0][row]=kv.x; sT1t[c4+1][row]=kv.y;
            sT1t[c4+2][row]=kv.z; sT1t[c4+3][row]=kv.w;
        }
        __syncthreads();
#pragma unroll 4
        for (int i=0;i<128;i++){
            float kv = sT1t[i][lane];
#pragma unroll
            for (int q=0;q<4;q++) acc[q] = fmaf(sT0[warp*4+q][i], kv, acc[q]);
        }
        __syncthreads();
    }
    float tmp = temp[hd];
#pragma unroll
    for (int q=0;q<4;q++){
        int c = warp*4+q;
        float s = acc[q]/(sn[c]*sn[32+lane]) * tmp;
        float m = s;
#pragma unroll
        for (int o=16;o;o>>=1) m = fmaxf(m, __shfl_xor_sync(~0u,m,o));
        float e = exp_fast(s-m);
        float su = e;
#pragma unroll
        for (int o=16;o;o>>=1) su += __shfl_xor_sync(~0u,su,o);
        sS[c][lane] = e/su;
    }
    __syncthreads();

    // out = S @ V
    for (int l0=0;l0<LSEQ;l0+=128){
#pragma unroll
        for (int t=0;t<4;t++){
            int idx = tid + t*256;
            int row = idx>>5, c4 = (idx&31)<<2;
            *(float4*)&sT0[row][c4] = *(const float4*)&V[row*LSEQ + l0 + c4];
        }
        __syncthreads();
        int c = tid&31;
#pragma unroll
        for (int t=0;t<16;t++){
            int ll = (tid>>5) + t*8;
            float s = 0.f;
#pragma unroll
            for (int dd=0;dd<32;dd++) s = fmaf(sS[c][dd], sT0[dd][ll], s);
            g_attno[((long)(b*LSEQ + l0 + ll))*HID + hd*32 + c] = s;
        }
        __syncthreads();
    }
}

// ---------------- final residual + transpose to NCHW ----------------
__global__ void final_k(float* __restrict__ out){
    __shared__ float tile[32][33];
    int b = blockIdx.z, l0 = blockIdx.x*32, c0 = blockIdx.y*32;
    int tx = threadIdx.x, ty = threadIdx.y;
#pragma unroll
    for (int j=0;j<4;j++){
        int l = l0+ty+j*8, c = c0+tx;
        long idx = ((long)(b*1024 + l))*256 + c;
        tile[ty+j*8][tx] = g_xh1[idx] + g_mod[b*1536 + 1280 + c]*g_projo[idx];
    }
    __syncthreads();
#pragma unroll
    for (int j=0;j<4;j++){
        int c = c0+ty+j*8;
        out[((long)(b*256 + c))<<10 | (l0+tx)] = tile[tx][ty+j*8];
    }
}

// ---------------- launch ----------------
extern "C" void kernel_launch(void* const* d_in, const int* in_sizes, int n_in,
                              void* d_out, int out_size){
    const float* x        = (const float*)d_in[0];
    const float* t        = (const float*)d_in[2];
    const float* g1       = (const float*)d_in[3];
    const float* b1       = (const float*)d_in[4];
    const float* W_ada    = (const float*)d_in[5];
    const float* b_ada    = (const float*)d_in[6];
    const float* W_in     = (const float*)d_in[7];
    const float* conv_w   = (const float*)d_in[8];
    const float* conv_b   = (const float*)d_in[9];
    const float* x_proj_w = (const float*)d_in[10];
    const float* dt_proj_w= (const float*)d_in[11];
    const float* dt_proj_b= (const float*)d_in[12];
    const float* A_logs   = (const float*)d_in[13];
    const float* Ds       = (const float*)d_in[14];
    const float* og       = (const float*)d_in[15];
    const float* ob       = (const float*)d_in[16];
    const float* W_out    = (const float*)d_in[17];
    const float* temp     = (const float*)d_in[18];
    const float* qkv_w    = (const float*)d_in[19];
    const float* dwconv_w = (const float*)d_in[20];
    const float* proj_w   = (const float*)d_in[21];
    float* out = (float*)d_out;

    float *p_silut, *p_mod, *p_xht, *p_h1, *p_xm, *p_z, *p_xc, *p_xs, *p_xdbl,
          *p_ys, *p_yln, *p_xh1, *p_h2, *p_qkv1, *p_qkv2, *p_attno, *p_projo,
          *p_qkvwT, *p_projwT, *p_xprojT;
    cudaGetSymbolAddress((void**)&p_silut, g_silut);
    cudaGetSymbolAddress((void**)&p_mod,   g_mod);
    cudaGetSymbolAddress((void**)&p_xht,   g_xht);
    cudaGetSymbolAddress((void**)&p_h1,    g_h1);
    cudaGetSymbolAddress((void**)&p_xm,    g_xm);
    cudaGetSymbolAddress((void**)&p_z,     g_z);
    cudaGetSymbolAddress((void**)&p_xc,    g_xc);
    cudaGetSymbolAddress((void**)&p_xs,    g_xs);
    cudaGetSymbolAddress((void**)&p_xdbl,  g_xdbl);
    cudaGetSymbolAddress((void**)&p_ys,    g_ys);
    cudaGetSymbolAddress((void**)&p_yln,   g_yln);
    cudaGetSymbolAddress((void**)&p_xh1,   g_xh1);
    cudaGetSymbolAddress((void**)&p_h2,    g_h2);
    cudaGetSymbolAddress((void**)&p_qkv1,  g_qkv1);
    cudaGetSymbolAddress((void**)&p_qkv2,  g_qkv2);
    cudaGetSymbolAddress((void**)&p_attno, g_attno);
    cudaGetSymbolAddress((void**)&p_projo, g_projo);
    cudaGetSymbolAddress((void**)&p_qkvwT, g_qkvwT);
    cudaGetSymbolAddress((void**)&p_projwT,g_projwT);
    cudaGetSymbolAddress((void**)&p_xprojT,g_xprojT);

    // prep
    silu_t_k<<<32,256>>>(t);
    transpose_w_k<<<dim3(768,1),256>>>(qkv_w, p_qkvwT, 768, 256);
    transpose_w_k<<<dim3(256,1),256>>>(proj_w, p_projwT, 256, 256);
    transpose_w_k<<<dim3(96,4),256>>>(x_proj_w, p_xprojT, 48, 512);
    transpose_x_k<<<dim3(32,8,8),dim3(32,8)>>>(x);

    // mod = silu(t) @ W_ada + b_ada   (M=8,N=1536,K=1024)
    gemm_kernel<<<dim3(24,1,1),256>>>(p_silut, W_ada, p_mod, nullptr, b_ada, nullptr,
                                      8, 1536, 1024, 1024, 1536, 0,0,0,0, 5);
    // h1 = modulate(LN(xht,g1,b1))
    ln_mod_k<<<1024,256>>>(p_xht, g1, b1, 0, 256, 1e-5f, 1, p_h1);
    // in_proj: (8192x256)@(256x1024) -> xm NCHW + z
    gemm_kernel<<<dim3(16,128,1),256>>>(p_h1, W_in, p_xm, p_z, nullptr, nullptr,
                                        NPIX, 1024, 256, 256, 1024, 0,0,0,0, 1);
    // conv + silu
    dwconv_k<<<BATCH*DINNER,256>>>(p_xm, conv_w, conv_b, p_xc, DINNER, 1);
    // xs
    build_xs_k<<<dim3(32,16,32),dim3(32,8)>>>();
    // x_dbl per (b,k): (1024x512)@(512x48)
    gemm_kernel<<<dim3(1,16,32),256>>>(p_xs, p_xprojT, p_xdbl, nullptr, nullptr, nullptr,
                                       1024, 48, 512, 512, 48,
                                       (long)1024*512, (long)512*48, (long)1024*48, 4, 0);
    // scan
    scan_kernel<<<128,128>>>(dt_proj_w, dt_proj_b, A_logs, Ds);
    // combine + LN + gate
    combine_ln_k<<<NPIX,128>>>(og, ob);
    // out_proj + residual gate: xh1 = xht + g_msa * (yln @ W_out)
    gemm_kernel<<<dim3(4,128,1),256>>>(p_yln, W_out, p_xh1, nullptr, p_xht, p_mod+512,
                                       NPIX, 256, 512, 512, 256, 0,0,0,0, 2);
    // h2 = modulate(LN(xh1))
    ln_mod_k<<<1024,256>>>(p_xh1, nullptr, nullptr, 768, 1024, 1e-6f, 0, p_h2);
    // qkv 1x1 -> NCHW
    gemm_kernel<<<dim3(12,128,1),256>>>(p_h2, p_qkvwT, p_qkv1, nullptr, nullptr, nullptr,
                                        NPIX, 768, 256, 256, 768, 0,0,0,0, 3);
    // dw conv (no bias/act)
    dwconv_k<<<BATCH*768,256>>>(p_qkv1, dwconv_w, nullptr, p_qkv2, 768, 0);
    // attention
    attn_kernel<<<64,256>>>(temp);
    // proj 1x1
    gemm_kernel<<<dim3(4,128,1),256>>>(p_attno, p_projwT, p_projo, nullptr, nullptr, nullptr,
                                       NPIX, 256, 256, 256, 256, 0,0,0,0, 0);
    // final
    final_k<<<dim3(32,8,8),dim3(32,8)>>>(out);
}

// round 3
// speedup vs baseline: 1.2311x; 1.2311x over previous
#include <cuda_runtime.h>
#include <cuda_bf16.h>

#define BATCH   8
#define HID     256
#define DINNER  512
#define DSTATE  16
#define DTRANK  16
#define LSEQ    1024
#define NPIX    (BATCH*LSEQ)

// ---------------- scratch (device globals) ----------------
__device__ float g_silut[BATCH*1024];
__device__ float g_mod  [BATCH*6*HID];
__device__ float g_xht  [NPIX*HID];
__device__ float g_h1   [NPIX*HID];
__device__ float g_xm   [BATCH*DINNER*LSEQ];          // NCHW
__device__ float g_z    [NPIX*DINNER];                // (B,L,512)
__device__ float g_xc   [BATCH*DINNER*LSEQ];          // NCHW
__device__ float g_xs   [BATCH*4*LSEQ*DINNER];        // (b,k,l,d)
__device__ float g_xdbl [BATCH*4*LSEQ*48];            // (b,k,l,48)
__device__ float g_ys   [BATCH*4*LSEQ*DINNER];        // (b,k,l,d)
__device__ float g_yln  [NPIX*DINNER];
__device__ float g_xh1  [NPIX*HID];
__device__ float g_h2   [NPIX*HID];
__device__ float g_qkv1 [BATCH*768*LSEQ];
__device__ float g_qkv2 [BATCH*768*LSEQ];
__device__ float g_attno[NPIX*HID];
__device__ float g_projo[NPIX*HID];
__device__ float g_qkvwT[256*768];
__device__ float g_projwT[256*256];
__device__ float g_xprojT[4*512*48];

// ---------------- fast exp ----------------
__device__ __forceinline__ float exp2_fast(float y){
    y = fminf(fmaxf(y, -126.f), 126.f);
    float r = rintf(y);
    float f = y - r;
    float p =              1.5403530e-4f;
    p = fmaf(p, f, 1.3333558e-3f);
    p = fmaf(p, f, 9.6181291e-3f);
    p = fmaf(p, f, 5.5504109e-2f);
    p = fmaf(p, f, 2.4022651e-1f);
    p = fmaf(p, f, 6.9314718e-1f);
    p = fmaf(p, f, 1.0f);
    return p * __int_as_float(((int)r + 127) << 23);
}
__device__ __forceinline__ float exp_fast(float x){ return exp2_fast(x * 1.4426950408889634f); }

__device__ __forceinline__ unsigned cvt_tf32(float x){
    unsigned r;
    asm("cvt.rna.tf32.f32 %0, %1;" : "=r"(r) : "f"(x));
    return r;
}

// ---------------- small kernels ----------------
__global__ void silu_t_k(const float* __restrict__ t){
    int i = blockIdx.x*blockDim.x + threadIdx.x;
    if (i < BATCH*1024){ float v = t[i]; g_silut[i] = v/(1.f+expf(-v)); }
}

__global__ void transpose_w_k(const float* __restrict__ in, float* __restrict__ out, int R, int C){
    int z = blockIdx.y;
    const float* ip = in + (long)z*R*C;
    float* op = out + (long)z*R*C;
    int i = blockIdx.x*blockDim.x + threadIdx.x;
    if (i < R*C){ int r = i/C, c = i%C; op[c*R + r] = ip[i]; }
}

__global__ void transpose_x_k(const float* __restrict__ x){
    __shared__ float tile[32][33];
    int b = blockIdx.z, l0 = blockIdx.x*32, c0 = blockIdx.y*32;
    int tx = threadIdx.x, ty = threadIdx.y;
#pragma unroll
    for (int j=0;j<4;j++)
        tile[ty+j*8][tx] = x[((long)(b*HID + c0+ty+j*8))<<10 | (l0+tx)];
    __syncthreads();
#pragma unroll
    for (int j=0;j<4;j++)
        g_xht[((long)(b*LSEQ + l0+ty+j*8))*HID + c0+tx] = tile[tx][ty+j*8];
}

// LN + modulate; one warp per pixel
__global__ void ln_mod_k(const float* __restrict__ xin, const float* __restrict__ g,
                         const float* __restrict__ bt, int sh_off, int sc_off,
                         float eps, int affine, float* __restrict__ out){
    int warp = threadIdx.x>>5, lane = threadIdx.x&31;
    int pix = blockIdx.x*8 + warp, b = pix>>10;
    const float* row = xin + (long)pix*HID;
    float v[8]; float s=0.f, sq=0.f;
#pragma unroll
    for (int i=0;i<8;i++){ v[i]=row[lane+i*32]; s+=v[i]; sq+=v[i]*v[i]; }
#pragma unroll
    for (int o=16;o;o>>=1){ s+=__shfl_xor_sync(~0u,s,o); sq+=__shfl_xor_sync(~0u,sq,o); }
    float mu = s*(1.f/HID), var = sq*(1.f/HID)-mu*mu, rstd = rsqrtf(var+eps);
#pragma unroll
    for (int i=0;i<8;i++){
        int ch = lane+i*32;
        float y = (v[i]-mu)*rstd;
        if (affine) y = y*g[ch]+bt[ch];
        out[(long)pix*HID+ch] = y*(1.f+g_mod[b*1536+sc_off+ch]) + g_mod[b*1536+sh_off+ch];
    }
}

// ---------------- FFMA GEMM (tiny mod GEMM only), mode 5: +bias ----------------
__global__ void gemm_kernel(const float* __restrict__ A, const float* __restrict__ B,
                            float* __restrict__ C, const float* __restrict__ aux0,
                            int M, int N, int K, int lda, int ldb){
    __shared__ float sA[16][64];
    __shared__ float sB[16][64];
    int bn = blockIdx.x*64, bm = blockIdx.y*64;
    int tid = threadIdx.x, tx = tid&15, ty = tid>>4;
    float acc[4][4];
#pragma unroll
    for (int i=0;i<4;i++)
#pragma unroll
        for (int j=0;j<4;j++) acc[i][j]=0.f;
    for (int k0=0;k0<K;k0+=16){
        int am = bm + (tid>>2), ak0 = (tid&3)<<2;
        float4 av = make_float4(0.f,0.f,0.f,0.f);
        if (am < M) av = *(const float4*)&A[(long)am*lda + k0 + ak0];
        sA[ak0+0][tid>>2]=av.x; sA[ak0+1][tid>>2]=av.y;
        sA[ak0+2][tid>>2]=av.z; sA[ak0+3][tid>>2]=av.w;
        int bkk = tid>>4, bn0 = (tid&15)<<2;
        const float* Brow = &B[(long)(k0+bkk)*ldb + bn + bn0];
#pragma unroll
        for (int u=0;u<4;u++)
            sB[bkk][bn0+u] = (bn+bn0+u < N) ? Brow[u] : 0.f;
        __syncthreads();
#pragma unroll
        for (int kk=0;kk<16;kk++){
            float4 a = *(const float4*)&sA[kk][ty*4];
            float4 bv= *(const float4*)&sB[kk][tx*4];
#pragma unroll
            for (int i=0;i<4;i++){
                float av2 = (i==0)?a.x:(i==1)?a.y:(i==2)?a.z:a.w;
                acc[i][0]=fmaf(av2,bv.x,acc[i][0]); acc[i][1]=fmaf(av2,bv.y,acc[i][1]);
                acc[i][2]=fmaf(av2,bv.z,acc[i][2]); acc[i][3]=fmaf(av2,bv.w,acc[i][3]);
            }
        }
        __syncthreads();
    }
#pragma unroll
    for (int i=0;i<4;i++){
        int m = bm + ty*4 + i;
        if (m >= M) continue;
#pragma unroll
        for (int j=0;j<4;j++){
            int n = bn + tx*4 + j;
            if (n >= N) continue;
            C[(long)m*N+n] = acc[i][j] + aux0[n];
        }
    }
}

// ---------------- TF32 tensor-core GEMM ----------------
// Tile 128(M) x 64(N) x 32(K); 8 warps (4x2); warp tile 32x32; m16n8k8.
// modes: 0 plain row-major, 1 in_proj split (xm NCHW / z row-major),
//        2 residual+gate row-major, 3 NCHW scatter (768 ch)
__global__ void __launch_bounds__(256)
mma_gemm(const float* __restrict__ A, const float* __restrict__ B,
         float* __restrict__ C, float* __restrict__ C2,
         const float* __restrict__ aux0, const float* __restrict__ aux1,
         int M, int N, int K, int lda, int ldb,
         long Astride, long Bstride, long Cstride, int bmod, int mode){
    __shared__ __align__(16) char smem_raw[64*132*4];   // 33792 B
    unsigned* sAu = (unsigned*)smem_raw;                 // [128][36]
    unsigned* sBu = (unsigned*)(smem_raw + 128*36*4);    // [32][68]
    float*    sT  = (float*)smem_raw;                    // [64][132] (epilogue)

    int z = blockIdx.z;
    A += (long)z*Astride;
    B += (long)(bmod ? (z % bmod) : z)*Bstride;

    int tid = threadIdx.x, lane = tid&31, warp = tid>>5;
    int wm = warp>>1, wn = warp&1;
    int m_base = blockIdx.y*128, n_base = blockIdx.x*64;
    int gid = lane>>2, tig = lane&3;

    float acc[2][4][4];
#pragma unroll
    for (int mi=0;mi<2;mi++)
#pragma unroll
        for (int nj=0;nj<4;nj++)
#pragma unroll
            for (int r=0;r<4;r++) acc[mi][nj][r]=0.f;

    for (int k0=0;k0<K;k0+=32){
        // stage A: 128x32
#pragma unroll
        for (int t=0;t<4;t++){
            int idx = t*256 + tid;
            int row = idx>>3, c4 = (idx&7)<<2;
            float4 v = *(const float4*)&A[(long)(m_base+row)*lda + k0 + c4];
            unsigned* dst = &sAu[row*36 + c4];
            dst[0]=cvt_tf32(v.x); dst[1]=cvt_tf32(v.y);
            dst[2]=cvt_tf32(v.z); dst[3]=cvt_tf32(v.w);
        }
        // stage B: 32x64 (guard N)
#pragma unroll
        for (int t=0;t<2;t++){
            int idx = t*256 + tid;
            int row = idx>>4, c4 = (idx&15)<<2;
            int gn = n_base + c4;
            float4 v;
            if (gn+3 < N) v = *(const float4*)&B[(long)(k0+row)*ldb + gn];
            else {
                const float* br = &B[(long)(k0+row)*ldb];
                v.x = (gn  <N)?br[gn  ]:0.f; v.y = (gn+1<N)?br[gn+1]:0.f;
                v.z = (gn+2<N)?br[gn+2]:0.f; v.w = (gn+3<N)?br[gn+3]:0.f;
            }
            unsigned* dst = &sBu[row*68 + c4];
            dst[0]=cvt_tf32(v.x); dst[1]=cvt_tf32(v.y);
            dst[2]=cvt_tf32(v.z); dst[3]=cvt_tf32(v.w);
        }
        __syncthreads();
#pragma unroll
        for (int kk=0;kk<32;kk+=8){
            unsigned a[2][4], bfr[4][2];
#pragma unroll
            for (int mi=0;mi<2;mi++){
                int r = wm*32 + mi*16 + gid;
                a[mi][0] = sAu[ r   *36 + kk + tig];
                a[mi][1] = sAu[(r+8)*36 + kk + tig];
                a[mi][2] = sAu[ r   *36 + kk + 4 + tig];
                a[mi][3] = sAu[(r+8)*36 + kk + 4 + tig];
            }
#pragma unroll
            for (int nj=0;nj<4;nj++){
                int cb = wn*32 + nj*8 + gid;
                bfr[nj][0] = sBu[(kk   + tig)*68 + cb];
                bfr[nj][1] = sBu[(kk+4 + tig)*68 + cb];
            }
#pragma unroll
            for (int mi=0;mi<2;mi++)
#pragma unroll
                for (int nj=0;nj<4;nj++){
                    asm volatile(
                        "mma.sync.aligned.m16n8k8.row.col.f32.tf32.tf32.f32 "
                        "{%0,%1,%2,%3}, {%4,%5,%6,%7}, {%8,%9}, {%0,%1,%2,%3};"
                        : "+f"(acc[mi][nj][0]), "+f"(acc[mi][nj][1]),
                          "+f"(acc[mi][nj][2]), "+f"(acc[mi][nj][3])
                        : "r"(a[mi][0]), "r"(a[mi][1]), "r"(a[mi][2]), "r"(a[mi][3]),
                          "r"(bfr[nj][0]), "r"(bfr[nj][1]));
                }
        }
        __syncthreads();
    }

    int b = m_base >> 10, l0 = m_base & 1023;

    if (mode==0 || mode==2 || (mode==1 && n_base >= 512)){
        // row-major outputs
#pragma unroll
        for (int mi=0;mi<2;mi++){
#pragma unroll
            for (int nj=0;nj<4;nj++){
                int r = m_base + wm*32 + mi*16 + gid;
                int c = n_base + wn*32 + nj*8 + tig*2;
#pragma unroll
                for (int half=0; half<2; half++){
                    int rr = r + half*8;
                    float v0 = acc[mi][nj][half*2+0];
                    float v1 = acc[mi][nj][half*2+1];
                    if (mode==2){
                        int bb = rr>>10;
                        float gte0 = aux1[bb*1536 + c];
                        float gte1 = aux1[bb*1536 + c + 1];
                        v0 = aux0[(long)rr*N + c]     + gte0*v0;
                        v1 = aux0[(long)rr*N + c + 1] + gte1*v1;
                        *(float2*)&C[(long)rr*N + c] = make_float2(v0, v1);
                    } else if (mode==1){
                        *(float2*)&C2[(long)rr*512 + (c-512)] = make_float2(v0, v1);
                    } else {
                        if (c < N){
                            if (c+1 < N) *(float2*)&C[z*Cstride + (long)rr*N + c] = make_float2(v0, v1);
                            else C[z*Cstride + (long)rr*N + c] = v0;
                        }
                    }
                }
            }
        }
    } else {
        // NCHW scatter: stage transpose in smem, write coalesced along l
        int Cch = (mode==1) ? 512 : 768;
#pragma unroll
        for (int mi=0;mi<2;mi++){
            int r0 = wm*32 + mi*16 + gid;
#pragma unroll
            for (int nj=0;nj<4;nj++){
                int c0 = wn*32 + nj*8 + tig*2;
                sT[(c0+0)*132 + r0  ] = acc[mi][nj][0];
                sT[(c0+1)*132 + r0  ] = acc[mi][nj][1];
                sT[(c0+0)*132 + r0+8] = acc[mi][nj][2];
                sT[(c0+1)*132 + r0+8] = acc[mi][nj][3];
            }
        }
        __syncthreads();
#pragma unroll
        for (int t=0;t<8;t++){
            int idx = t*256 + tid;
            int nrow = idx>>5, m4 = (idx&31)<<2;
            float4 v = *(const float4*)&sT[nrow*132 + m4];
            int ch = n_base + nrow;
            *(float4*)&C[(((long)(b*Cch + ch))<<10) + l0 + m4] = v;
        }
    }
}

// ---------------- depthwise 3x3 SAME ----------------
__global__ void dwconv_k(const float* __restrict__ in, const float* __restrict__ w,
                         const float* __restrict__ bias, float* __restrict__ out,
                         int C, int act){
    int bc = blockIdx.x, ch = bc % C;
    const float* p = in + (long)bc*LSEQ;
    const float* wc = w + ch*9;
    float w0=wc[0],w1=wc[1],w2=wc[2],w3=wc[3],w4=wc[4],w5=wc[5],w6=wc[6],w7=wc[7],w8=wc[8];
    float bv = bias ? bias[ch] : 0.f;
    for (int idx = threadIdx.x; idx < LSEQ; idx += blockDim.x){
        int y = idx>>5, x = idx&31;
        float s = bv;
        bool yu=y>0, yd=y<31, xl=x>0, xr=x<31;
        if (yu){ if (xl) s=fmaf(w0,p[idx-33],s); s=fmaf(w1,p[idx-32],s); if (xr) s=fmaf(w2,p[idx-31],s); }
        if (xl) s=fmaf(w3,p[idx-1],s);
        s=fmaf(w4,p[idx],s);
        if (xr) s=fmaf(w5,p[idx+1],s);
        if (yd){ if (xl) s=fmaf(w6,p[idx+31],s); s=fmaf(w7,p[idx+32],s); if (xr) s=fmaf(w8,p[idx+33],s); }
        if (act) s = s/(1.f+expf(-s));
        out[(long)bc*LSEQ + idx] = s;
    }
}

// ---------------- build xs (b,k,l,d) ----------------
__device__ __forceinline__ int lmap_dir(int k, int i){
    int ti = ((i&31)<<5) | (i>>5);
    if (k==0) return i;
    if (k==1) return ti;
    if (k==2) return 1023-i;
    return 1023-ti;
}
__global__ void build_xs_k(void){
    __shared__ float tile[32][33];
    int bk = blockIdx.z, b = bk>>2, k = bk&3;
    int i0 = blockIdx.x*32, d0 = blockIdx.y*32;
    int tx = threadIdx.x, ty = threadIdx.y;
#pragma unroll
    for (int j=0;j<4;j++)
        tile[ty+j*8][tx] = g_xc[((long)(b*DINNER + d0+ty+j*8))<<10 | (i0+tx)];
    __syncthreads();
#pragma unroll
    for (int j=0;j<4;j++){
        int l = lmap_dir(k, i0+ty+j*8);
        g_xs[(((long)bk<<10) + l)*DINNER + d0+tx] = tile[tx][ty+j*8];
    }
}

// ---------------- selective scan ----------------
__global__ void __launch_bounds__(128, 1)
scan_kernel(const float* __restrict__ dt_w, const float* __restrict__ dt_b,
            const float* __restrict__ A_logs, const float* __restrict__ Ds){
    int blk = blockIdx.x;
    int bk = blk>>2, sub = blk&3, k = bk&3;
    int d = sub*128 + threadIdx.x;
    int gd = k*DINNER + d;
    float w[DTRANK];
#pragma unroll
    for (int r=0;r<DTRANK;r++) w[r] = dt_w[gd*DTRANK+r];
    float bias = dt_b[gd];
    float A2[DSTATE];
#pragma unroll
    for (int n=0;n<DSTATE;n++) A2[n] = -expf(A_logs[gd*DSTATE+n]) * 1.4426950408889634f;
    float Dv = Ds[gd];
    float h[DSTATE];
#pragma unroll
    for (int n=0;n<DSTATE;n++) h[n]=0.f;

    const float* xrow = g_xs   + ((long)bk<<10)*DINNER;
    const float* drow = g_xdbl + ((long)bk<<10)*48;
    float*       yrow = g_ys   + ((long)bk<<10)*DINNER;

    __shared__ float sd[2][48];
    if (threadIdx.x < 48) sd[0][threadIdx.x] = drow[threadIdx.x];
    __syncthreads();
    float xnext = xrow[d];

    for (int l=0;l<LSEQ;l++){
        int cur = l&1;
        if (l+1 < LSEQ && threadIdx.x < 48)
            sd[cur^1][threadIdx.x] = drow[(l+1)*48 + threadIdx.x];
        float x = xnext;
        if (l+1 < LSEQ) xnext = xrow[(l+1)*DINNER + d];
        float v = bias;
#pragma unroll
        for (int r=0;r<DTRANK;r++) v = fmaf(sd[cur][r], w[r], v);
        float dt = fmaxf(v,0.f) + log1pf(exp_fast(-fabsf(v)));
        float dtx = dt*x;
        float y = Dv*x;
#pragma unroll
        for (int n=0;n<DSTATE;n++){
            float dA = exp2_fast(dt*A2[n]);
            h[n] = fmaf(dA, h[n], dtx*sd[cur][16+n]);
            y = fmaf(h[n], sd[cur][32+n], y);
        }
        yrow[l*DINNER + d] = y;
        __syncthreads();
    }
}

// ---------------- combine dirs + LN + silu(z) gate ----------------
__global__ void combine_ln_k(const float* __restrict__ og, const float* __restrict__ ob){
    int bl = blockIdx.x, b = bl>>10, l = bl&1023;
    int lt = ((l&31)<<5) | (l>>5);
    const float* r0 = g_ys + (((long)(b*4+0)<<10) + l)        *DINNER;
    const float* r1 = g_ys + (((long)(b*4+1)<<10) + lt)       *DINNER;
    const float* r2 = g_ys + (((long)(b*4+2)<<10) + (1023-l)) *DINNER;
    const float* r3 = g_ys + (((long)(b*4+3)<<10) + (1023-lt))*DINNER;
    float v[4]; float s=0.f, sq=0.f;
#pragma unroll
    for (int i=0;i<4;i++){
        int d = threadIdx.x + i*128;
        v[i] = r0[d]+r1[d]+r2[d]+r3[d];
        s += v[i]; sq += v[i]*v[i];
    }
    __shared__ float red[2][4];
    int warp = threadIdx.x>>5, lane = threadIdx.x&31;
#pragma unroll
    for (int o=16;o;o>>=1){ s+=__shfl_xor_sync(~0u,s,o); sq+=__shfl_xor_sync(~0u,sq,o); }
    if (!lane){ red[0][warp]=s; red[1][warp]=sq; }
    __syncthreads();
    s = red[0][0]+red[0][1]+red[0][2]+red[0][3];
    sq= red[1][0]+red[1][1]+red[1][2]+red[1][3];
    float mu = s*(1.f/DINNER), var = sq*(1.f/DINNER)-mu*mu, rstd = rsqrtf(var+1e-5f);
#pragma unroll
    for (int i=0;i<4;i++){
        int d = threadIdx.x + i*128;
        float y = (v[i]-mu)*rstd*og[d] + ob[d];
        float zz = g_z[(long)bl*DINNER + d];
        g_yln[(long)bl*DINNER + d] = y * (zz/(1.f+expf(-zz)));
    }
}

// ---------------- transposed attention ----------------
__global__ void attn_kernel(const float* __restrict__ temp){
    int b = blockIdx.x>>3, hd = blockIdx.x&7;
    const float* Q  = g_qkv2 + ((long)(b*768) + hd*32)*LSEQ;
    const float* Kp = Q + 256*LSEQ;
    const float* V  = Q + 512*LSEQ;
    __shared__ float sn[64];
    __shared__ float sS[32][33];
    __shared__ float sT0[32][128];
    __shared__ float sT1t[128][33];
    int tid = threadIdx.x, warp = tid>>5, lane = tid&31;

#pragma unroll
    for (int rr=0;rr<8;rr++){
        int row = warp*8 + rr;
        const float* base = (row<32) ? (Q + row*LSEQ) : (Kp + (row-32)*LSEQ);
        float s = 0.f;
        for (int i=lane;i<LSEQ;i+=32){ float x = base[i]; s = fmaf(x,x,s); }
#pragma unroll
        for (int o=16;o;o>>=1) s += __shfl_xor_sync(~0u,s,o);
        if (!lane) sn[row] = fmaxf(sqrtf(s), 1e-12f);
    }
    __syncthreads();

    float acc[4] = {0.f,0.f,0.f,0.f};
    for (int l0=0;l0<LSEQ;l0+=128){
#pragma unroll
        for (int t=0;t<4;t++){
            int idx = tid + t*256;
            int row = idx>>5, c4 = (idx&31)<<2;
            float4 qv = *(const float4*)&Q [row*LSEQ + l0 + c4];
            float4 kv = *(const float4*)&Kp[row*LSEQ + l0 + c4];
            *(float4*)&sT0[row][c4] = qv;
            sT1t[c4+0][row]=kv.x; sT1t[c4+1][row]=kv.y;
            sT1t[c4+2][row]=kv.z; sT1t[c4+3][row]=kv.w;
        }
        __syncthreads();
#pragma unroll 4
        for (int i=0;i<128;i++){
            float kv = sT1t[i][lane];
#pragma unroll
            for (int q=0;q<4;q++) acc[q] = fmaf(sT0[warp*4+q][i], kv, acc[q]);
        }
        __syncthreads();
    }
    float tmp = temp[hd];
#pragma unroll
    for (int q=0;q<4;q++){
        int c = warp*4+q;
        float s = acc[q]/(sn[c]*sn[32+lane]) * tmp;
        float m = s;
#pragma unroll
        for (int o=16;o;o>>=1) m = fmaxf(m, __shfl_xor_sync(~0u,m,o));
        float e = exp_fast(s-m);
        float su = e;
#pragma unroll
        for (int o=16;o;o>>=1) su += __shfl_xor_sync(~0u,su,o);
        sS[c][lane] = e/su;
    }
    __syncthreads();

    for (int l0=0;l0<LSEQ;l0+=128){
#pragma unroll
        for (int t=0;t<4;t++){
            int idx = tid + t*256;
            int row = idx>>5, c4 = (idx&31)<<2;
            *(float4*)&sT0[row][c4] = *(const float4*)&V[row*LSEQ + l0 + c4];
        }
        __syncthreads();
        int c = tid&31;
#pragma unroll
        for (int t=0;t<16;t++){
            int ll = (tid>>5) + t*8;
            float s = 0.f;
#pragma unroll
            for (int dd=0;dd<32;dd++) s = fmaf(sS[c][dd], sT0[dd][ll], s);
            g_attno[((long)(b*LSEQ + l0 + ll))*HID + hd*32 + c] = s;
        }
        __syncthreads();
    }
}

// ---------------- final residual + transpose to NCHW ----------------
__global__ void final_k(float* __restrict__ out){
    __shared__ float tile[32][33];
    int b = blockIdx.z, l0 = blockIdx.x*32, c0 = blockIdx.y*32;
    int tx = threadIdx.x, ty = threadIdx.y;
#pragma unroll
    for (int j=0;j<4;j++){
        int l = l0+ty+j*8, c = c0+tx;
        long idx = ((long)(b*1024 + l))*256 + c;
        tile[ty+j*8][tx] = g_xh1[idx] + g_mod[b*1536 + 1280 + c]*g_projo[idx];
    }
    __syncthreads();
#pragma unroll
    for (int j=0;j<4;j++){
        int c = c0+ty+j*8;
        out[((long)(b*256 + c))<<10 | (l0+tx)] = tile[tx][ty+j*8];
    }
}

// ---------------- launch ----------------
extern "C" void kernel_launch(void* const* d_in, const int* in_sizes, int n_in,
                              void* d_out, int out_size){
    const float* x        = (const float*)d_in[0];
    const float* t        = (const float*)d_in[2];
    const float* g1       = (const float*)d_in[3];
    const float* b1       = (const float*)d_in[4];
    const float* W_ada    = (const float*)d_in[5];
    const float* b_ada    = (const float*)d_in[6];
    const float* W_in     = (const float*)d_in[7];
    const float* conv_w   = (const float*)d_in[8];
    const float* conv_b   = (const float*)d_in[9];
    const float* x_proj_w = (const float*)d_in[10];
    const float* dt_proj_w= (const float*)d_in[11];
    const float* dt_proj_b= (const float*)d_in[12];
    const float* A_logs   = (const float*)d_in[13];
    const float* Ds       = (const float*)d_in[14];
    const float* og       = (const float*)d_in[15];
    const float* ob       = (const float*)d_in[16];
    const float* W_out    = (const float*)d_in[17];
    const float* temp     = (const float*)d_in[18];
    const float* qkv_w    = (const float*)d_in[19];
    const float* dwconv_w = (const float*)d_in[20];
    const float* proj_w   = (const float*)d_in[21];
    float* out = (float*)d_out;

    float *p_silut, *p_mod, *p_xht, *p_h1, *p_xm, *p_z, *p_xc, *p_xs, *p_xdbl,
          *p_ys, *p_yln, *p_xh1, *p_h2, *p_qkv1, *p_qkv2, *p_attno, *p_projo,
          *p_qkvwT, *p_projwT, *p_xprojT;
    cudaGetSymbolAddress((void**)&p_silut, g_silut);
    cudaGetSymbolAddress((void**)&p_mod,   g_mod);
    cudaGetSymbolAddress((void**)&p_xht,   g_xht);
    cudaGetSymbolAddress((void**)&p_h1,    g_h1);
    cudaGetSymbolAddress((void**)&p_xm,    g_xm);
    cudaGetSymbolAddress((void**)&p_z,     g_z);
    cudaGetSymbolAddress((void**)&p_xc,    g_xc);
    cudaGetSymbolAddress((void**)&p_xs,    g_xs);
    cudaGetSymbolAddress((void**)&p_xdbl,  g_xdbl);
    cudaGetSymbolAddress((void**)&p_ys,    g_ys);
    cudaGetSymbolAddress((void**)&p_yln,   g_yln);
    cudaGetSymbolAddress((void**)&p_xh1,   g_xh1);
    cudaGetSymbolAddress((void**)&p_h2,    g_h2);
    cudaGetSymbolAddress((void**)&p_qkv1,  g_qkv1);
    cudaGetSymbolAddress((void**)&p_qkv2,  g_qkv2);
    cudaGetSymbolAddress((void**)&p_attno, g_attno);
    cudaGetSymbolAddress((void**)&p_projo, g_projo);
    cudaGetSymbolAddress((void**)&p_qkvwT, g_qkvwT);
    cudaGetSymbolAddress((void**)&p_projwT,g_projwT);
    cudaGetSymbolAddress((void**)&p_xprojT,g_xprojT);

    // prep
    silu_t_k<<<32,256>>>(t);
    transpose_w_k<<<dim3(768,1),256>>>(qkv_w, p_qkvwT, 768, 256);
    transpose_w_k<<<dim3(256,1),256>>>(proj_w, p_projwT, 256, 256);
    transpose_w_k<<<dim3(96,4),256>>>(x_proj_w, p_xprojT, 48, 512);
    transpose_x_k<<<dim3(32,8,8),dim3(32,8)>>>(x);

    // mod = silu(t) @ W_ada + b_ada (tiny FFMA)
    gemm_kernel<<<dim3(24,1,1),256>>>(p_silut, W_ada, p_mod, b_ada, 8, 1536, 1024, 1024, 1536);
    // h1 = modulate(LN(xht,g1,b1))
    ln_mod_k<<<1024,256>>>(p_xht, g1, b1, 0, 256, 1e-5f, 1, p_h1);
    // in_proj -> xm NCHW + z
    mma_gemm<<<dim3(16,64,1),256>>>(p_h1, W_in, p_xm, p_z, nullptr, nullptr,
                                    NPIX, 1024, 256, 256, 1024, 0,0,0,0, 1);
    // conv + silu
    dwconv_k<<<BATCH*DINNER,256>>>(p_xm, conv_w, conv_b, p_xc, DINNER, 1);
    // xs
    build_xs_k<<<dim3(32,16,32),dim3(32,8)>>>();
    // x_dbl per (b,k): (1024x512)@(512x48)
    mma_gemm<<<dim3(1,8,32),256>>>(p_xs, p_xprojT, p_xdbl, nullptr, nullptr, nullptr,
                                   1024, 48, 512, 512, 48,
                                   (long)1024*512, (long)512*48, (long)1024*48, 4, 0);
    // scan
    scan_kernel<<<128,128>>>(dt_proj_w, dt_proj_b, A_logs, Ds);
    // combine + LN + gate
    combine_ln_k<<<NPIX,128>>>(og, ob);
    // out_proj + residual gate
    mma_gemm<<<dim3(4,64,1),256>>>(p_yln, W_out, p_xh1, nullptr, p_xht, p_mod+512,
                                   NPIX, 256, 512, 512, 256, 0,0,0,0, 2);
    // h2 = modulate(LN(xh1))
    ln_mod_k<<<1024,256>>>(p_xh1, nullptr, nullptr, 768, 1024, 1e-6f, 0, p_h2);
    // qkv 1x1 -> NCHW
    mma_gemm<<<dim3(12,64,1),256>>>(p_h2, p_qkvwT, p_qkv1, nullptr, nullptr, nullptr,
                                    NPIX, 768, 256, 256, 768, 0,0,0,0, 3);
    // dw conv
    dwconv_k<<<BATCH*768,256>>>(p_qkv1, dwconv_w, nullptr, p_qkv2, 768, 0);
    // attention
    attn_kernel<<<64,256>>>(temp);
    // proj 1x1
    mma_gemm<<<dim3(4,64,1),256>>>(p_attno, p_projwT, p_projo, nullptr, nullptr, nullptr,
                                   NPIX, 256, 256, 256, 256, 0,0,0,0, 0);
    // final
    final_k<<<dim3(32,8,8),dim3(32,8)>>>(out);
}